// round 9
// baseline (speedup 1.0000x reference)
#include <cuda_runtime.h>
#include <math.h>

#define BATCH 65536
#define FULL 0xffffffffu

typedef unsigned long long u64;

// -------- device scratch (allocation-free rule: __device__ globals) --------
__device__ float g_f [(size_t)BATCH * 420];   // DyConv output
__device__ float g_hh[(size_t)BATCH * 256];   // relu(f@W1+b1)

// ---------------- packed f32x2 ops on b64 registers ----------------
__device__ __forceinline__ u64 pack2(float x, float y) {
    u64 r; asm("mov.b64 %0, {%1, %2};" : "=l"(r) : "f"(x), "f"(y)); return r;
}
__device__ __forceinline__ u64 dup2(float s) { return pack2(s, s); }
__device__ __forceinline__ void unpack2(u64 v, float& x, float& y) {
    asm("mov.b64 {%0, %1}, %2;" : "=f"(x), "=f"(y) : "l"(v));
}
__device__ __forceinline__ u64 fma2u(u64 a, u64 b, u64 c) {
    u64 d; asm("fma.rn.f32x2 %0, %1, %2, %3;" : "=l"(d) : "l"(a), "l"(b), "l"(c)); return d;
}
__device__ __forceinline__ u64 add2u(u64 a, u64 b) {
    u64 d; asm("add.rn.f32x2 %0, %1, %2;" : "=l"(d) : "l"(a), "l"(b)); return d;
}
__device__ __forceinline__ ulonglong2 lds2(const u64* p) {
    return *reinterpret_cast<const ulonglong2*>(p);
}

// ---------------- tf32 helpers (3xTF32 compensated GEMM) ----------------
__device__ __forceinline__ void split_tf32(float x, unsigned& hi, unsigned& lo) {
    asm("cvt.rna.tf32.f32 %0, %1;" : "=r"(hi) : "f"(x));
    float r = x - __uint_as_float(hi);
    asm("cvt.rna.tf32.f32 %0, %1;" : "=r"(lo) : "f"(r));
}
__device__ __forceinline__ void mma_tf32(float* c, const unsigned* a, const unsigned* b) {
    asm volatile(
        "mma.sync.aligned.m16n8k8.row.col.f32.tf32.tf32.f32 "
        "{%0,%1,%2,%3},{%4,%5,%6,%7},{%8,%9},{%0,%1,%2,%3};"
        : "+f"(c[0]), "+f"(c[1]), "+f"(c[2]), "+f"(c[3])
        : "r"(a[0]), "r"(a[1]), "r"(a[2]), "r"(a[3]), "r"(b[0]), "r"(b[1]));
}

// ---- shuffle-scan series_decomp helper (replicate-pad MA-25) ----
__device__ __forceinline__ float decomp25(float val, int lane, int hi, int loix,
                                          int lom1, float fc0, float fc29) {
    float cs = val;
    #pragma unroll
    for (int off = 1; off < 32; off <<= 1) {
        float o = __shfl_up_sync(FULL, cs, off);
        if (lane >= off) cs += o;
    }
    float cshi = __shfl_sync(FULL, cs, hi);
    float cslo = __shfl_sync(FULL, cs, loix);
    float ssum = cshi - ((lom1 >= 0) ? cslo : 0.f);
    float x0  = __shfl_sync(FULL, val, 0);
    float x29 = __shfl_sync(FULL, val, 29);
    return val - (ssum + fc0 * x0 + fc29 * x29) * (1.f / 25.f);
}

// ============================================================================
// Kernel A: register-resident per-sample pipeline, FFMA2 + LDS.128 tiles.
// 1 warp = 1 sample, lane t in [0,30) holds the 14-channel row.
// ============================================================================
__global__ __launch_bounds__(256) void kA(
    const float* __restrict__ x,
    const float* __restrict__ W_emb, const float* __restrict__ b_emb,
    const float* __restrict__ Wq, const float* __restrict__ bq,
    const float* __restrict__ Wk, const float* __restrict__ bk,
    const float* __restrict__ Wv, const float* __restrict__ bv,
    const float* __restrict__ Wo, const float* __restrict__ bo,
    const float* __restrict__ Wff1, const float* __restrict__ Wff2,
    const float* __restrict__ gnorm, const float* __restrict__ bnorm,
    const float* __restrict__ Wdy, const float* __restrict__ bdy,
    const float* __restrict__ channels)
{
    // 8-slot padded pair tiles for LDS.128
    __shared__ __align__(16) float2 sWeP[336];   // [ (ci*3+tp)*8 + op ], op<7 valid
    __shared__ __align__(16) float  sbe[14];
    __shared__ __align__(16) float  sWq[112], sWk[112], sWv[112];   // [d*8+h]
    __shared__ __align__(16) float  sbq[8], sbk[8], sbv[8];
    __shared__ __align__(16) float2 sWoP[64];    // [h*8+dp], dp<7 valid
    __shared__ __align__(16) float  sbo[14];
    __shared__ __align__(16) float2 sF1P[400];   // [f*8+dp]: (F1[2dp][f],F1[2dp+1][f])
    __shared__ __align__(16) float2 sF2P[400];   // [f*8+dp]: (F2[f][2dp],F2[f][2dp+1])
    __shared__ __align__(16) float  sg[14], sb[14];
    __shared__ __align__(16) float  sWdy[900], sbdy[30];
    __shared__ __align__(16) float2 sAdjP[112];  // [i*8+jp], jp<7 valid
    __shared__ __align__(16) float  scr[8][512]; // per-warp scratch (2048B)

    const int tid = threadIdx.x;
    for (int i = tid; i < 336; i += 256) {
        int ct = i >> 3, op = i & 7;
        float a = 0.f, b = 0.f;
        if (op < 7) { a = W_emb[(2*op)*42 + ct]; b = W_emb[(2*op+1)*42 + ct]; }
        sWeP[i] = make_float2(a, b);
    }
    for (int i = tid; i < 112; i += 256) { sWq[i]=Wq[i]; sWk[i]=Wk[i]; sWv[i]=Wv[i]; }
    for (int i = tid; i < 64; i += 256) {
        int h = i >> 3, dp = i & 7;
        float a = 0.f, b = 0.f;
        if (dp < 7) { a = Wo[h*14 + 2*dp]; b = Wo[h*14 + 2*dp + 1]; }
        sWoP[i] = make_float2(a, b);
    }
    for (int i = tid; i < 400; i += 256) {
        int f = i >> 3, dp = i & 7;
        float a1 = 0.f, b1v = 0.f, a2 = 0.f, b2v = 0.f;
        if (dp < 7) {
            a1 = Wff1[(2*dp)*50 + f]; b1v = Wff1[(2*dp+1)*50 + f];
            a2 = Wff2[f*14 + 2*dp];   b2v = Wff2[f*14 + 2*dp + 1];
        }
        sF1P[i] = make_float2(a1, b1v);
        sF2P[i] = make_float2(a2, b2v);
    }
    for (int i = tid; i < 900; i += 256) sWdy[i] = Wdy[i];
    if (tid < 30) sbdy[tid] = bdy[tid];
    if (tid < 14) { sbe[tid]=b_emb[tid]; sbo[tid]=bo[tid]; sg[tid]=gnorm[tid]; sb[tid]=bnorm[tid]; }
    if (tid < 8)  { sbq[tid]=bq[tid]; sbk[tid]=bk[tid]; sbv[tid]=bv[tid]; }
    if (tid < 14) {
        const float* row = channels + tid * 14;
        float mx = -1e30f;
        #pragma unroll
        for (int j = 0; j < 14; j++) mx = fmaxf(mx, row[j]);
        float s = 0.f;
        #pragma unroll
        for (int j = 0; j < 14; j++) s += expf(row[j] - mx);
        float inv = 1.f / s;
        #pragma unroll
        for (int j = 0; j < 7; j++)
            sAdjP[tid*8 + j] = make_float2(expf(row[2*j] - mx) * inv,
                                           expf(row[2*j+1] - mx) * inv);
        sAdjP[tid*8 + 7] = make_float2(0.f, 0.f);
    }
    __syncthreads();

    const int w    = tid >> 5;
    const int lane = tid & 31;
    const int t    = (lane < 30) ? lane : 0;
    const bool act = (lane < 30);
    const int smp  = blockIdx.x * 8 + w;
    u64* scrU = reinterpret_cast<u64*>(scr[w]);

    // ---- coalesced stage of x ----
    {
        const float4* xp = reinterpret_cast<const float4*>(x + (size_t)smp * 420);
        float4* sp = reinterpret_cast<float4*>(scr[w]);
        #pragma unroll
        for (int i = lane; i < 105; i += 32) sp[i] = xp[i];
    }
    __syncwarp();
    float xr[14];
    #pragma unroll
    for (int d = 0; d < 14; d++) xr[d] = scr[w][t*14 + d];
    __syncwarp();

    // ---- Conv1d embed (kernel 3, zero pad): packed output-channel pairs ----
    u64 xe2[7];
    {
        const u64* sbe2 = reinterpret_cast<const u64*>(sbe);
        #pragma unroll
        for (int op = 0; op < 7; op++) xe2[op] = sbe2[op];
        const u64* we = reinterpret_cast<const u64*>(sWeP);
        #pragma unroll
        for (int ci = 0; ci < 14; ci++) {
            float up = __shfl_up_sync(FULL, xr[ci], 1);
            float dn = __shfl_down_sync(FULL, xr[ci], 1);
            float xm  = (lane > 0)  ? up : 0.f;
            float xp2 = (lane < 29) ? dn : 0.f;
            float tap[3] = { xm, xr[ci], xp2 };
            #pragma unroll
            for (int tp = 0; tp < 3; tp++) {
                u64 xv2 = dup2(tap[tp]);
                const u64* wr = we + (ci*3 + tp) * 8;
                ulonglong2 w0 = lds2(wr), w1 = lds2(wr+2), w2 = lds2(wr+4);
                u64 w6 = wr[6];
                xe2[0] = fma2u(xv2, w0.x, xe2[0]);
                xe2[1] = fma2u(xv2, w0.y, xe2[1]);
                xe2[2] = fma2u(xv2, w1.x, xe2[2]);
                xe2[3] = fma2u(xv2, w1.y, xe2[3]);
                xe2[4] = fma2u(xv2, w2.x, xe2[4]);
                xe2[5] = fma2u(xv2, w2.y, xe2[5]);
                xe2[6] = fma2u(xv2, w6,   xe2[6]);
            }
        }
    }
    float xes[14];
    #pragma unroll
    for (int dp = 0; dp < 7; dp++) unpack2(xe2[dp], xes[2*dp], xes[2*dp+1]);

    // ---- QKV (packed head pairs; 2x LDS.128 per d per matrix) ----
    u64 q2[4], k2[4], v2[4];
    {
        const u64* bq2 = reinterpret_cast<const u64*>(sbq);
        const u64* bk2 = reinterpret_cast<const u64*>(sbk);
        const u64* bv2 = reinterpret_cast<const u64*>(sbv);
        #pragma unroll
        for (int hp = 0; hp < 4; hp++) { q2[hp]=bq2[hp]; k2[hp]=bk2[hp]; v2[hp]=bv2[hp]; }
        const u64* wq2 = reinterpret_cast<const u64*>(sWq);
        const u64* wk2 = reinterpret_cast<const u64*>(sWk);
        const u64* wv2 = reinterpret_cast<const u64*>(sWv);
        #pragma unroll
        for (int d = 0; d < 14; d++) {
            u64 xv2 = dup2(xes[d]);
            ulonglong2 qa = lds2(wq2 + d*4), qb = lds2(wq2 + d*4 + 2);
            ulonglong2 ka = lds2(wk2 + d*4), kb = lds2(wk2 + d*4 + 2);
            ulonglong2 va = lds2(wv2 + d*4), vb = lds2(wv2 + d*4 + 2);
            q2[0] = fma2u(xv2, qa.x, q2[0]); q2[1] = fma2u(xv2, qa.y, q2[1]);
            q2[2] = fma2u(xv2, qb.x, q2[2]); q2[3] = fma2u(xv2, qb.y, q2[3]);
            k2[0] = fma2u(xv2, ka.x, k2[0]); k2[1] = fma2u(xv2, ka.y, k2[1]);
            k2[2] = fma2u(xv2, kb.x, k2[2]); k2[3] = fma2u(xv2, kb.y, k2[3]);
            v2[0] = fma2u(xv2, va.x, v2[0]); v2[1] = fma2u(xv2, va.y, v2[1]);
            v2[2] = fma2u(xv2, vb.x, v2[2]); v2[3] = fma2u(xv2, vb.y, v2[3]);
        }
    }
    float v[8];
    #pragma unroll
    for (int hp = 0; hp < 4; hp++) unpack2(v2[hp], v[2*hp], v[2*hp+1]);

    // stage q,k: layout [t*4 + hp] (u64) -> 2x STS.128 each
    u64* qsU = scrU;          // 120 u64
    u64* ksU = scrU + 128;    // 120 u64
    if (act) {
        *reinterpret_cast<ulonglong2*>(qsU + t*4)     = make_ulonglong2(q2[0], q2[1]);
        *reinterpret_cast<ulonglong2*>(qsU + t*4 + 2) = make_ulonglong2(q2[2], q2[3]);
        *reinterpret_cast<ulonglong2*>(ksU + t*4)     = make_ulonglong2(k2[0], k2[1]);
        *reinterpret_cast<ulonglong2*>(ksU + t*4 + 2) = make_ulonglong2(k2[2], k2[3]);
    }
    __syncwarp();

    // ---- circular correlation corr[tau] = sum_{t,h} q[t][h]*k[(t-tau)%30][h] ----
    float mv;
    {
        u64 acc2[4] = {};
        #pragma unroll
        for (int tq = 0; tq < 30; tq++) {
            int src = tq - t; if (src < 0) src += 30;
            ulonglong2 qa = lds2(qsU + tq*4), qb = lds2(qsU + tq*4 + 2);
            ulonglong2 ka = lds2(ksU + src*4), kb = lds2(ksU + src*4 + 2);
            acc2[0] = fma2u(qa.x, ka.x, acc2[0]);
            acc2[1] = fma2u(qa.y, ka.y, acc2[1]);
            acc2[2] = fma2u(qb.x, kb.x, acc2[2]);
            acc2[3] = fma2u(qb.y, kb.y, acc2[3]);
        }
        u64 s2 = add2u(add2u(acc2[0], acc2[1]), add2u(acc2[2], acc2[3]));
        float sx, sy; unpack2(s2, sx, sy);
        mv = act ? (sx + sy) * 0.125f : -1e30f;
    }

    // ---- warp-parallel top-3 with first-index tie-break ----
    float wv0, wv1, wv2; int dl0, dl1, dl2;
    {
        float mrun = mv;
        #pragma unroll
        for (int p = 0; p < 3; p++) {
            float bv = mrun; int bi = lane;
            #pragma unroll
            for (int off = 16; off; off >>= 1) {
                float vo = __shfl_xor_sync(FULL, bv, off);
                int   io = __shfl_xor_sync(FULL, bi, off);
                if (vo > bv || (vo == bv && io < bi)) { bv = vo; bi = io; }
            }
            if (p == 0) { wv0 = bv; dl0 = bi; }
            else if (p == 1) { wv1 = bv; dl1 = bi; }
            else { wv2 = bv; dl2 = bi; }
            if (lane == bi) mrun = -1e30f;
        }
    }
    float e1 = expf(wv1 - wv0);
    float e2 = expf(wv2 - wv0);
    float inv = 1.f / (1.f + e1 + e2);
    float w0 = inv, w1 = e1 * inv, w2 = e2 * inv;

    // ---- delay aggregation via shuffles ----
    float agg[8];
    {
        int s0 = t + dl0; if (s0 >= 30) s0 -= 30;
        int s1 = t + dl1; if (s1 >= 30) s1 -= 30;
        int s2 = t + dl2; if (s2 >= 30) s2 -= 30;
        #pragma unroll
        for (int h = 0; h < 8; h++) {
            float a = w0 * __shfl_sync(FULL, v[h], s0);
            a      += w1 * __shfl_sync(FULL, v[h], s1);
            a      += w2 * __shfl_sync(FULL, v[h], s2);
            agg[h] = a;
        }
    }

    // ---- x1 = xe + agg @ Wo + bo ----
    u64 x1u[7];
    {
        const u64* sbo2 = reinterpret_cast<const u64*>(sbo);
        #pragma unroll
        for (int dp = 0; dp < 7; dp++) x1u[dp] = add2u(xe2[dp], sbo2[dp]);
        const u64* wo = reinterpret_cast<const u64*>(sWoP);
        #pragma unroll
        for (int h = 0; h < 8; h++) {
            u64 a2 = dup2(agg[h]);
            const u64* wr = wo + h*8;
            ulonglong2 w0v = lds2(wr), w1v = lds2(wr+2), w2v = lds2(wr+4);
            u64 w6 = wr[6];
            x1u[0] = fma2u(a2, w0v.x, x1u[0]);
            x1u[1] = fma2u(a2, w0v.y, x1u[1]);
            x1u[2] = fma2u(a2, w1v.x, x1u[2]);
            x1u[3] = fma2u(a2, w1v.y, x1u[3]);
            x1u[4] = fma2u(a2, w2v.x, x1u[4]);
            x1u[5] = fma2u(a2, w2v.y, x1u[5]);
            x1u[6] = fma2u(a2, w6,    x1u[6]);
        }
    }

    // ---- series_decomp 1 ----
    const float fc0  = (t < 12) ? (float)(12 - t) : 0.f;
    const float fc29 = (t > 17) ? (float)(t - 17) : 0.f;
    const int hi   = (t + 12 > 29) ? 29 : t + 12;
    const int lom1 = t - 13;
    const int loix = (lom1 < 0) ? 0 : lom1;
    u64 xdu[7];
    #pragma unroll
    for (int dp = 0; dp < 7; dp++) {
        float vx, vy; unpack2(x1u[dp], vx, vy);
        float dx = decomp25(vx, lane, hi, loix, lom1, fc0, fc29);
        float dy = decomp25(vy, lane, hi, loix, lom1, fc0, fc29);
        xdu[dp] = pack2(dx, dy);
    }

    // ---- FFN: x2 = xd + gelu_exact(xd @ F1) @ F2 ----
    u64 x2u[7];
    {
        u64 y2[7] = {};
        const u64* f1 = reinterpret_cast<const u64*>(sF1P);
        const u64* f2 = reinterpret_cast<const u64*>(sF2P);
        #pragma unroll 5
        for (int f = 0; f < 50; f++) {
            const u64* r1 = f1 + f*8;
            ulonglong2 a0 = lds2(r1), a1 = lds2(r1+2), a2l = lds2(r1+4);
            u64 a6 = r1[6];
            u64 h2 = fma2u(xdu[0], a0.x, 0ULL);
            h2 = fma2u(xdu[1], a0.y, h2);
            h2 = fma2u(xdu[2], a1.x, h2);
            h2 = fma2u(xdu[3], a1.y, h2);
            h2 = fma2u(xdu[4], a2l.x, h2);
            h2 = fma2u(xdu[5], a2l.y, h2);
            h2 = fma2u(xdu[6], a6,   h2);
            float hx, hy; unpack2(h2, hx, hy);
            float hs = hx + hy;
            float g = 0.5f * hs * (1.f + erff(hs * 0.70710678118654752f));
            u64 g2 = dup2(g);
            const u64* r2 = f2 + f*8;
            ulonglong2 b0 = lds2(r2), b1v = lds2(r2+2), b2v = lds2(r2+4);
            u64 b6 = r2[6];
            y2[0] = fma2u(g2, b0.x, y2[0]);
            y2[1] = fma2u(g2, b0.y, y2[1]);
            y2[2] = fma2u(g2, b1v.x, y2[2]);
            y2[3] = fma2u(g2, b1v.y, y2[3]);
            y2[4] = fma2u(g2, b2v.x, y2[4]);
            y2[5] = fma2u(g2, b2v.y, y2[5]);
            y2[6] = fma2u(g2, b6,   y2[6]);
        }
        #pragma unroll
        for (int dp = 0; dp < 7; dp++) x2u[dp] = add2u(xdu[dp], y2[dp]);
    }

    // ---- series_decomp 2 + layernorm ----
    float x3x[7], x3y[7];
    #pragma unroll
    for (int dp = 0; dp < 7; dp++) {
        float vx, vy; unpack2(x2u[dp], vx, vy);
        x3x[dp] = decomp25(vx, lane, hi, loix, lom1, fc0, fc29);
        x3y[dp] = decomp25(vy, lane, hi, loix, lom1, fc0, fc29);
    }
    {
        float m = 0.f;
        #pragma unroll
        for (int dp = 0; dp < 7; dp++) m += x3x[dp] + x3y[dp];
        m *= (1.f / 14.f);
        float var = 0.f;
        #pragma unroll
        for (int dp = 0; dp < 7; dp++) {
            float dx = x3x[dp] - m, dy = x3y[dp] - m;
            var += dx * dx + dy * dy;
        }
        var *= (1.f / 14.f);
        float invs = rsqrtf(var + 1e-5f);
        #pragma unroll
        for (int dp = 0; dp < 7; dp++) {
            x3x[dp] = (x3x[dp] - m) * invs * sg[2*dp]   + sb[2*dp];
            x3y[dp] = (x3y[dp] - m) * invs * sg[2*dp+1] + sb[2*dp+1];
        }
    }

    // ---- DyConv: stage x3 pairs at [t*8+dp], accumulate over m (lane = l) ----
    __syncwarp();
    u64* x3sU = scrU;   // 240 u64 used
    if (act) {
        u64 p0 = pack2(x3x[0], x3y[0]), p1 = pack2(x3x[1], x3y[1]);
        u64 p2 = pack2(x3x[2], x3y[2]), p3 = pack2(x3x[3], x3y[3]);
        u64 p4 = pack2(x3x[4], x3y[4]), p5 = pack2(x3x[5], x3y[5]);
        u64 p6 = pack2(x3x[6], x3y[6]);
        *reinterpret_cast<ulonglong2*>(x3sU + t*8)     = make_ulonglong2(p0, p1);
        *reinterpret_cast<ulonglong2*>(x3sU + t*8 + 2) = make_ulonglong2(p2, p3);
        *reinterpret_cast<ulonglong2*>(x3sU + t*8 + 4) = make_ulonglong2(p4, p5);
        x3sU[t*8 + 6] = p6;
    }
    __syncwarp();
    u64 accd2[7];
    {
        u64 bias2 = dup2(sbdy[t]);
        #pragma unroll
        for (int dp = 0; dp < 7; dp++) accd2[dp] = bias2;
        #pragma unroll
        for (int m = 0; m < 30; m++) {
            u64 wm2 = dup2(sWdy[m*30 + t]);
            const u64* xb = x3sU + m*8;
            ulonglong2 xa = lds2(xb), xbv = lds2(xb+2), xc = lds2(xb+4);
            u64 x6 = xb[6];
            accd2[0] = fma2u(xa.x, wm2, accd2[0]);
            accd2[1] = fma2u(xa.y, wm2, accd2[1]);
            accd2[2] = fma2u(xbv.x, wm2, accd2[2]);
            accd2[3] = fma2u(xbv.y, wm2, accd2[3]);
            accd2[4] = fma2u(xc.x, wm2, accd2[4]);
            accd2[5] = fma2u(xc.y, wm2, accd2[5]);
            accd2[6] = fma2u(x6,   wm2, accd2[6]);
        }
    }

    // ---- dy = relu(adj @ h2) -> g_f ----
    {
        float* fo = g_f + (size_t)smp * 420;
        const u64* adj = reinterpret_cast<const u64*>(sAdjP);
        #pragma unroll
        for (int i = 0; i < 14; i++) {
            const u64* ar = adj + i*8;
            ulonglong2 a0 = lds2(ar), a1 = lds2(ar+2), a2l = lds2(ar+4);
            u64 a6 = ar[6];
            u64 acc = fma2u(a0.x, accd2[0], 0ULL);
            acc = fma2u(a0.y, accd2[1], acc);
            acc = fma2u(a1.x, accd2[2], acc);
            acc = fma2u(a1.y, accd2[3], acc);
            acc = fma2u(a2l.x, accd2[4], acc);
            acc = fma2u(a2l.y, accd2[5], acc);
            acc = fma2u(a6,   accd2[6], acc);
            float ax, ay; unpack2(acc, ax, ay);
            if (act) fo[i*30 + t] = fmaxf(ax + ay, 0.f);
        }
    }
}

// ============================================================================
// Kernel B (tensor): hh = relu(f @ W1 + b1)  M=65536, K=420, N=256
// ============================================================================
__global__ __launch_bounds__(256) void kB(const float* __restrict__ W1,
                                          const float* __restrict__ b1)
{
    __shared__ __align__(16) float As[128][36];
    __shared__ __align__(16) float Bs[64][36];
    const int tid = threadIdx.x;
    const int lane = tid & 31, wid = tid >> 5;
    const int wm = wid >> 1, wn = wid & 1;
    const size_t mbase = (size_t)blockIdx.x * 128;
    const int nbase = blockIdx.y * 64;
    float c[2][4][4] = {};

    for (int k0 = 0; k0 < 448; k0 += 32) {
        {
            int m = tid >> 1;
            const float4* gr = reinterpret_cast<const float4*>(g_f + (mbase + m) * 420);
            #pragma unroll
            for (int i = 0; i < 4; i++) {
                int qf = (tid & 1) * 4 + i;
                int kq = (k0 >> 2) + qf;
                float4 vv = (kq < 105) ? gr[kq] : make_float4(0.f,0.f,0.f,0.f);
                *reinterpret_cast<float4*>(&As[m][qf*4]) = vv;
            }
        }
        {
            int kl = tid >> 3;
            int gk = k0 + kl;
            #pragma unroll
            for (int half = 0; half < 2; half++) {
                int n4 = ((tid & 7) + 8*half) * 4;
                float4 vv = make_float4(0.f,0.f,0.f,0.f);
                if (gk < 420)
                    vv = *reinterpret_cast<const float4*>(W1 + (size_t)gk*256 + nbase + n4);
                Bs[n4+0][kl] = vv.x; Bs[n4+1][kl] = vv.y;
                Bs[n4+2][kl] = vv.z; Bs[n4+3][kl] = vv.w;
            }
        }
        __syncthreads();
        #pragma unroll
        for (int ks = 0; ks < 4; ks++) {
            int kk = ks * 8;
            unsigned ah[2][4], al[2][4], bh[4][2], bl[4][2];
            #pragma unroll
            for (int mt = 0; mt < 2; mt++) {
                int r = wm*32 + mt*16 + (lane>>2);
                split_tf32(As[r  ][kk + (lane&3)    ], ah[mt][0], al[mt][0]);
                split_tf32(As[r+8][kk + (lane&3)    ], ah[mt][1], al[mt][1]);
                split_tf32(As[r  ][kk + (lane&3) + 4], ah[mt][2], al[mt][2]);
                split_tf32(As[r+8][kk + (lane&3) + 4], ah[mt][3], al[mt][3]);
            }
            #pragma unroll
            for (int nt = 0; nt < 4; nt++) {
                int nn = wn*32 + nt*8 + (lane>>2);
                split_tf32(Bs[nn][kk + (lane&3)    ], bh[nt][0], bl[nt][0]);
                split_tf32(Bs[nn][kk + (lane&3) + 4], bh[nt][1], bl[nt][1]);
            }
            #pragma unroll
            for (int mt = 0; mt < 2; mt++)
                #pragma unroll
                for (int nt = 0; nt < 4; nt++) {
                    mma_tf32(c[mt][nt], ah[mt], bh[nt]);
                    mma_tf32(c[mt][nt], ah[mt], bl[nt]);
                    mma_tf32(c[mt][nt], al[mt], bh[nt]);
                }
        }
        __syncthreads();
    }
    #pragma unroll
    for (int mt = 0; mt < 2; mt++) {
        int r0 = wm*32 + mt*16 + (lane>>2);
        #pragma unroll
        for (int nt = 0; nt < 4; nt++) {
            int cl = nbase + wn*32 + nt*8 + 2*(lane&3);
            float b0 = b1[cl], b1v = b1[cl+1];
            float2 lo = make_float2(fmaxf(c[mt][nt][0] + b0, 0.f), fmaxf(c[mt][nt][1] + b1v, 0.f));
            float2 hi = make_float2(fmaxf(c[mt][nt][2] + b0, 0.f), fmaxf(c[mt][nt][3] + b1v, 0.f));
            *reinterpret_cast<float2*>(g_hh + (mbase + r0    ) * 256 + cl) = lo;
            *reinterpret_cast<float2*>(g_hh + (mbase + r0 + 8) * 256 + cl) = hi;
        }
    }
}

// ============================================================================
// Kernel C (tensor, fused LN head): hr = [hh|f]@[W2;Wres]+b2+bres, then
// out = LN64(hr) @ W3 + b3 computed from register fragments (no g_hr).
// ============================================================================
__global__ __launch_bounds__(256) void kC(const float* __restrict__ W2,
                                          const float* __restrict__ b2,
                                          const float* __restrict__ Wres,
                                          const float* __restrict__ bres,
                                          const float* __restrict__ g_ln,
                                          const float* __restrict__ b_ln,
                                          const float* __restrict__ W3,
                                          const float* __restrict__ b3,
                                          float* __restrict__ out)
{
    __shared__ __align__(16) float As[128][36];
    __shared__ __align__(16) float Bs[64][36];
    __shared__ float sbb[64];        // b2+bres
    __shared__ float sgw[64];        // g_ln*W3
    __shared__ float sp[128][2][3];  // per-row half partials (sv, sq, sg)
    __shared__ float sconst[2];      // G, cb
    const int tid = threadIdx.x;
    const int lane = tid & 31, wid = tid >> 5;
    const int wm = wid >> 1, wn = wid & 1;
    const size_t mbase = (size_t)blockIdx.x * 128;
    float c[2][4][4] = {};

    if (tid < 64) {
        sbb[tid] = b2[tid] + bres[tid];
        sgw[tid] = g_ln[tid] * W3[tid];
    }

    for (int k0 = 0; k0 < 704; k0 += 32) {
        {
            int m = tid >> 1;
            const float* hrow = g_hh + (mbase + m) * 256;
            const float* frow = g_f  + (mbase + m) * 420;
            #pragma unroll
            for (int i = 0; i < 4; i++) {
                int qf = (tid & 1) * 4 + i;
                int gk = k0 + qf*4;
                float4 vv = make_float4(0.f,0.f,0.f,0.f);
                if (gk < 256) vv = *reinterpret_cast<const float4*>(hrow + gk);
                else { int kf = gk - 256; if (kf < 420) vv = *reinterpret_cast<const float4*>(frow + kf); }
                *reinterpret_cast<float4*>(&As[m][qf*4]) = vv;
            }
        }
        {
            int kl = tid >> 3;
            int gk = k0 + kl;
            #pragma unroll
            for (int half = 0; half < 2; half++) {
                int n4 = ((tid & 7) + 8*half) * 4;
                float4 vv = make_float4(0.f,0.f,0.f,0.f);
                if (gk < 256) vv = *reinterpret_cast<const float4*>(W2 + (size_t)gk*64 + n4);
                else { int kf = gk - 256; if (kf < 420) vv = *reinterpret_cast<const float4*>(Wres + (size_t)kf*64 + n4); }
                Bs[n4+0][kl] = vv.x; Bs[n4+1][kl] = vv.y;
                Bs[n4+2][kl] = vv.z; Bs[n4+3][kl] = vv.w;
            }
        }
        __syncthreads();
        #pragma unroll
        for (int ks = 0; ks < 4; ks++) {
            int kk = ks * 8;
            unsigned ah[2][4], al[2][4], bh[4][2], bl[4][2];
            #pragma unroll
            for (int mt = 0; mt < 2; mt++) {
                int r = wm*32 + mt*16 + (lane>>2);
                split_tf32(As[r  ][kk + (lane&3)    ], ah[mt][0], al[mt][0]);
                split_tf32(As[r+8][kk + (lane&3)    ], ah[mt][1], al[mt][1]);
                split_tf32(As[r  ][kk + (lane&3) + 4], ah[mt][2], al[mt][2]);
                split_tf32(As[r+8][kk + (lane&3) + 4], ah[mt][3], al[mt][3]);
            }
            #pragma unroll
            for (int nt = 0; nt < 4; nt++) {
                int nn = wn*32 + nt*8 + (lane>>2);
                split_tf32(Bs[nn][kk + (lane&3)    ], bh[nt][0], bl[nt][0]);
                split_tf32(Bs[nn][kk + (lane&3) + 4], bh[nt][1], bl[nt][1]);
            }
            #pragma unroll
            for (int mt = 0; mt < 2; mt++)
                #pragma unroll
                for (int nt = 0; nt < 4; nt++) {
                    mma_tf32(c[mt][nt], ah[mt], bh[nt]);
                    mma_tf32(c[mt][nt], ah[mt], bl[nt]);
                    mma_tf32(c[mt][nt], al[mt], bh[nt]);
                }
        }
        __syncthreads();
    }

    // ---- fused epilogue: partial LN sums per (row, wn-half) ----
    #pragma unroll
    for (int mt = 0; mt < 2; mt++) {
        #pragma unroll
        for (int rb = 0; rb < 2; rb++) {
            float sv = 0.f, sq = 0.f, sgd = 0.f;
            #pragma unroll
            for (int nt = 0; nt < 4; nt++) {
                int cl = wn*32 + nt*8 + 2*(lane&3);
                float v0 = c[mt][nt][2*rb]     + sbb[cl];
                float v1 = c[mt][nt][2*rb + 1] + sbb[cl+1];
                sv += v0 + v1;
                sq += v0*v0 + v1*v1;
                sgd += v0*sgw[cl] + v1*sgw[cl+1];
            }
            sv += __shfl_xor_sync(FULL, sv, 1);
            sq += __shfl_xor_sync(FULL, sq, 1);
            sgd += __shfl_xor_sync(FULL, sgd, 1);
            sv += __shfl_xor_sync(FULL, sv, 2);
            sq += __shfl_xor_sync(FULL, sq, 2);
            sgd += __shfl_xor_sync(FULL, sgd, 2);
            if ((lane & 3) == 0) {
                int row = wm*32 + mt*16 + rb*8 + (lane>>2);
                sp[row][wn][0] = sv;
                sp[row][wn][1] = sq;
                sp[row][wn][2] = sgd;
            }
        }
    }
    if (tid == 0) {
        float G = 0.f, cb = b3[0];
        for (int d = 0; d < 64; d++) { G += sgw[d]; cb += b_ln[d] * W3[d]; }
        sconst[0] = G; sconst[1] = cb;
    }
    __syncthreads();
    if (tid < 128) {
        int row = tid;
        float sv  = sp[row][0][0] + sp[row][1][0];
        float sq  = sp[row][0][1] + sp[row][1][1];
        float sgd = sp[row][0][2] + sp[row][1][2];
        float m = sv * (1.f / 64.f);
        float var = sq * (1.f / 64.f) - m * m;
        float invs = rsqrtf(var + 1e-5f);
        out[mbase + row] = invs * (sgd - m * sconst[0]) + sconst[1];
    }
}

// ============================================================================
extern "C" void kernel_launch(void* const* d_in, const int* in_sizes, int n_in,
                              void* d_out, int out_size)
{
    (void)in_sizes; (void)n_in; (void)out_size;
    const float* x = (const float*)d_in[0];

    kA<<<BATCH / 8, 256>>>(x,
        (const float*)d_in[1],  (const float*)d_in[2],
        (const float*)d_in[3],  (const float*)d_in[4],
        (const float*)d_in[5],  (const float*)d_in[6],
        (const float*)d_in[7],  (const float*)d_in[8],
        (const float*)d_in[9],  (const float*)d_in[10],
        (const float*)d_in[11], (const float*)d_in[12],
        (const float*)d_in[13], (const float*)d_in[14],
        (const float*)d_in[15], (const float*)d_in[16],
        (const float*)d_in[17]);

    kB<<<dim3(BATCH / 128, 4), 256>>>((const float*)d_in[18], (const float*)d_in[19]);

    kC<<<BATCH / 128, 256>>>((const float*)d_in[20], (const float*)d_in[21],
                             (const float*)d_in[22], (const float*)d_in[23],
                             (const float*)d_in[24], (const float*)d_in[25],
                             (const float*)d_in[26], (const float*)d_in[27],
                             (float*)d_out);
}